// round 1
// baseline (speedup 1.0000x reference)
#include <cuda_runtime.h>
#include <cuda_bf16.h>

// Problem constants (fixed-shape problem)
#define E_MAX   250000
#define A_MAX   10000
// K_L = {256,192,128,64}; F_TOTAL = 256 + 3*192 + 5*128 + 7*64 = 1920
#define F_TOTAL 1920
#define PROD_SZ 640   // 256+192+128+64
#define SH_SZ   16    // 1+3+5+7

// Scratch (no allocations allowed -> __device__ globals)
__device__ int g_count[A_MAX];
__device__ int g_offsets[A_MAX];
__device__ int g_cursor[A_MAX];
__device__ int g_edge_order[E_MAX];

// ---------------------------------------------------------------------------
__global__ void reset_kernel(int nAtoms) {
    int i = blockIdx.x * blockDim.x + threadIdx.x;
    if (i < nAtoms) g_count[i] = 0;
}

__global__ void count_kernel(const int* __restrict__ centers, int E) {
    int e = blockIdx.x * blockDim.x + threadIdx.x;
    if (e < E) atomicAdd(&g_count[centers[e]], 1);
}

// Single-block exclusive scan over nAtoms (<= A_MAX) counts.
__global__ void scan_kernel(int nAtoms) {
    __shared__ int part[1024];
    const int tid = threadIdx.x;
    const int chunk = (nAtoms + 1023) >> 10;
    const int b = tid * chunk;
    const int e = min(b + chunk, nAtoms);

    int s = 0;
    for (int i = b; i < e; i++) s += g_count[i];
    part[tid] = s;
    __syncthreads();

    // Hillis-Steele inclusive scan
    for (int off = 1; off < 1024; off <<= 1) {
        int t = 0;
        if (tid >= off) t = part[tid - off];
        __syncthreads();
        part[tid] += t;
        __syncthreads();
    }
    int run = part[tid] - s;  // exclusive prefix for this thread's chunk
    for (int i = b; i < e; i++) {
        g_offsets[i] = run;
        g_cursor[i]  = run;
        run += g_count[i];
    }
}

__global__ void scatter_kernel(const int* __restrict__ centers, int E) {
    int e = blockIdx.x * blockDim.x + threadIdx.x;
    if (e < E) {
        int c = centers[e];
        int p = atomicAdd(&g_cursor[c], 1);
        g_edge_order[p] = e;
    }
}

// ---------------------------------------------------------------------------
// Main density kernel: one CTA per atom. Accumulate all edges of this atom in
// registers, write every output element exactly once (no float atomics).
//
// Flat channel layout f in [0, 1920):
//   l=0: f in [0,256)     m=0         k=f
//   l=1: f in [256,832)   m=(f-256)/192, k=(f-256)%192
//   l=2: f in [832,1472)  m=(f-832)/128, k=(f-832)%128
//   l=3: f in [1472,1920) m=(f-1472)/64, k=(f-1472)%64
// prod[] layout: l0 at 0, l1 at 256, l2 at 448, l3 at 576.
// sh[]   layout: l0 at 0, l1 at 1,   l2 at 4,   l3 at 9.
__global__ void __launch_bounds__(256)
density_kernel(const float* __restrict__ sh0, const float* __restrict__ sh1,
               const float* __restrict__ sh2, const float* __restrict__ sh3,
               const float* __restrict__ rb0, const float* __restrict__ rb1,
               const float* __restrict__ rb2, const float* __restrict__ rb3,
               const float* __restrict__ emb, const int* __restrict__ neighbors,
               float* __restrict__ out, int nAtoms)
{
    const int atom = blockIdx.x;
    const int tid  = threadIdx.x;

    __shared__ float sh_s[SH_SZ];
    __shared__ float prod_s[PROD_SZ];

    // Region bases in the flat output buffer
    const long B0 = 0;
    const long B1 = (long)nAtoms * 256;
    const long B2 = B1 + (long)nAtoms * 576;
    const long B3 = B2 + (long)nAtoms * 640;

    // Each thread t < 240 owns 8 consecutive flat channels [t*8, t*8+8).
    // All l/m/k boundaries are multiples of 8, so a chunk never straddles one.
    const bool active = (tid < 240);
    int shx = 0;        // index into sh_s
    int pq  = 0;        // float4 index into prod_s for first 4 channels
    long obase = 0;     // output element index for first channel (for this atom)
    if (active) {
        int f = tid * 8;
        int l, m, k;
        long base, stride;
        int pbase, shbase, kl;
        if (f < 256)       { l = 0; m = 0; k = f;
                             base = B0; stride = 256; pbase = 0;   shbase = 0; kl = 256; }
        else if (f < 832)  { int r = f - 256;  m = r / 192; k = r - 192 * m;
                             base = B1; stride = 576; pbase = 256; shbase = 1; kl = 192; }
        else if (f < 1472) { int r = f - 832;  m = r >> 7;  k = r & 127;
                             base = B2; stride = 640; pbase = 448; shbase = 4; kl = 128; }
        else               { int r = f - 1472; m = r >> 6;  k = r & 63;
                             base = B3; stride = 448; pbase = 576; shbase = 9; kl = 64;  }
        shx   = shbase + m;
        pq    = (pbase + k) >> 2;
        obase = base + (long)atom * stride + (long)m * kl + k;
    }

    float acc0 = 0.f, acc1 = 0.f, acc2 = 0.f, acc3 = 0.f;
    float acc4 = 0.f, acc5 = 0.f, acc6 = 0.f, acc7 = 0.f;

    const int start = g_offsets[atom];
    const int cnt   = g_count[atom];

    for (int j = 0; j < cnt; j++) {
        const int e   = g_edge_order[start + j];
        const int nbr = neighbors[e];

        // Stage spherical harmonics (16 values)
        if (tid < 16) {
            float v;
            if (tid == 0)      v = sh0[e];
            else if (tid < 4)  v = sh1[(long)e * 3 + (tid - 1)];
            else if (tid < 9)  v = sh2[(long)e * 5 + (tid - 4)];
            else               v = sh3[(long)e * 7 + (tid - 9)];
            sh_s[tid] = v;
        }

        // Stage prod[k] = rb_l[e][k] * emb[nbr][k]  (640 floats = 160 float4)
        if (tid < 160) {
            const float4* embv = (const float4*)(emb + (long)nbr * 256);
            float4 a, b; int p4;
            if (tid < 64)       { a = ((const float4*)(rb0 + (long)e * 256))[tid];
                                  b = embv[tid];            p4 = tid; }
            else if (tid < 112) { int t = tid - 64;
                                  a = ((const float4*)(rb1 + (long)e * 192))[t];
                                  b = embv[t];              p4 = 64 + t; }
            else if (tid < 144) { int t = tid - 112;
                                  a = ((const float4*)(rb2 + (long)e * 128))[t];
                                  b = embv[t];              p4 = 112 + t; }
            else                { int t = tid - 144;
                                  a = ((const float4*)(rb3 + (long)e * 64))[t];
                                  b = embv[t];              p4 = 144 + t; }
            float4 p;
            p.x = a.x * b.x; p.y = a.y * b.y; p.z = a.z * b.z; p.w = a.w * b.w;
            ((float4*)prod_s)[p4] = p;
        }
        __syncthreads();

        if (active) {
            const float s = sh_s[shx];
            const float4 p0 = ((const float4*)prod_s)[pq];
            const float4 p1 = ((const float4*)prod_s)[pq + 1];
            acc0 += s * p0.x; acc1 += s * p0.y; acc2 += s * p0.z; acc3 += s * p0.w;
            acc4 += s * p1.x; acc5 += s * p1.y; acc6 += s * p1.z; acc7 += s * p1.w;
        }
        __syncthreads();
    }

    if (active) {
        // obase is 8-aligned within a 16B-aligned buffer -> float4 stores ok
        float4* o = (float4*)(out + obase);
        o[0] = make_float4(acc0, acc1, acc2, acc3);
        o[1] = make_float4(acc4, acc5, acc6, acc7);
    }
}

// ---------------------------------------------------------------------------
extern "C" void kernel_launch(void* const* d_in, const int* in_sizes, int n_in,
                              void* d_out, int out_size)
{
    // Input order: setup_inputs interleaves (sh_0, rb_0, sh_1, rb_1, ...) but
    // the reference signature groups (sh_0..sh_3, rb_0..rb_3). Detect at
    // runtime: rb_0 has E*256 elements, sh_1 only E*3.
    const float* sh[4];
    const float* rb[4];
    const bool interleaved = ((long)in_sizes[1] > (long)in_sizes[0] * 8);
    for (int l = 0; l < 4; l++) {
        if (interleaved) {
            sh[l] = (const float*)d_in[2 * l];
            rb[l] = (const float*)d_in[2 * l + 1];
        } else {
            sh[l] = (const float*)d_in[l];
            rb[l] = (const float*)d_in[4 + l];
        }
    }
    const float* emb       = (const float*)d_in[8];
    const int*   centers   = (const int*)d_in[9];
    const int*   neighbors = (const int*)d_in[10];
    float*       out       = (float*)d_out;

    const int E      = in_sizes[9];            // centers element count
    const int nAtoms = in_sizes[8] / 256;      // emb is [A,1,256]

    const int TB = 256;
    reset_kernel  <<<(nAtoms + TB - 1) / TB, TB>>>(nAtoms);
    count_kernel  <<<(E + TB - 1) / TB, TB>>>(centers, E);
    scan_kernel   <<<1, 1024>>>(nAtoms);
    scatter_kernel<<<(E + TB - 1) / TB, TB>>>(centers, E);
    density_kernel<<<nAtoms, 256>>>(sh[0], sh[1], sh[2], sh[3],
                                    rb[0], rb[1], rb[2], rb[3],
                                    emb, neighbors, out, nAtoms);
}

// round 2
// speedup vs baseline: 1.3297x; 1.3297x over previous
#include <cuda_runtime.h>
#include <cuda_bf16.h>

// Problem constants (fixed-shape problem)
#define E_MAX   250000
#define A_MAX   10000
#define CHUNK   256    // edges staged per barrier round

// Scratch (no allocations allowed -> __device__ globals)
__device__ int g_count[A_MAX];
__device__ int g_offsets[A_MAX];
__device__ int g_cursor[A_MAX];
__device__ int g_edge_order[E_MAX];

// ---------------------------------------------------------------------------
__global__ void reset_kernel(int nAtoms) {
    int i = blockIdx.x * blockDim.x + threadIdx.x;
    if (i < nAtoms) g_count[i] = 0;
}

__global__ void count_kernel(const int* __restrict__ centers, int E) {
    int e = blockIdx.x * blockDim.x + threadIdx.x;
    if (e < E) atomicAdd(&g_count[centers[e]], 1);
}

// Single-block exclusive scan over nAtoms (<= A_MAX) counts.
__global__ void scan_kernel(int nAtoms) {
    __shared__ int part[1024];
    const int tid = threadIdx.x;
    const int chunk = (nAtoms + 1023) >> 10;
    const int b = tid * chunk;
    const int e = min(b + chunk, nAtoms);

    int s = 0;
    for (int i = b; i < e; i++) s += g_count[i];
    part[tid] = s;
    __syncthreads();

    for (int off = 1; off < 1024; off <<= 1) {
        int t = 0;
        if (tid >= off) t = part[tid - off];
        __syncthreads();
        part[tid] += t;
        __syncthreads();
    }
    int run = part[tid] - s;
    for (int i = b; i < e; i++) {
        g_offsets[i] = run;
        g_cursor[i]  = run;
        run += g_count[i];
    }
}

__global__ void scatter_kernel(const int* __restrict__ centers, int E) {
    int e = blockIdx.x * blockDim.x + threadIdx.x;
    if (e < E) {
        int c = centers[e];
        int p = atomicAdd(&g_cursor[c], 1);
        g_edge_order[p] = e;
    }
}

// ---------------------------------------------------------------------------
// Main density kernel: one CTA per atom, barrier-free inner loop.
// Thread t < 240 owns 8 consecutive flat channels [t*8, t*8+8). All l/m/k
// boundaries are multiples of 8, so a chunk never straddles one.
// Per edge, per thread: 1 broadcast LDG (sh), 2x LDG.128 (rb), 2x LDG.128
// (emb, L2-resident), 8 mul + 8 fma. Edge ids + neighbor ids are staged in
// SMEM once per CHUNK edges -> only 2 barriers per chunk.
__global__ void __launch_bounds__(256)
density_kernel(const float* __restrict__ sh0, const float* __restrict__ sh1,
               const float* __restrict__ sh2, const float* __restrict__ sh3,
               const float* __restrict__ rb0, const float* __restrict__ rb1,
               const float* __restrict__ rb2, const float* __restrict__ rb3,
               const float* __restrict__ emb, const int* __restrict__ neighbors,
               float* __restrict__ out, int nAtoms)
{
    const int atom = blockIdx.x;
    const int tid  = threadIdx.x;

    __shared__ int s_e[CHUNK];
    __shared__ int s_nbr[CHUNK];

    // Region bases in the flat output buffer
    const long B1 = (long)nAtoms * 256;
    const long B2 = B1 + (long)nAtoms * 576;
    const long B3 = B2 + (long)nAtoms * 640;

    const bool active = (tid < 240);

    // Per-thread static addressing state
    const float* shp = sh0;   // sh_l base + m offset applied via shoff
    int shstride = 1, shoff = 0;
    const float4* rbp = (const float4*)rb0;
    int rbstride4 = 64;       // k_l/4 float4s per edge row
    int kq = 0;               // float4 offset of this thread's k within the row
    long obase = 0;

    if (active) {
        int f = tid * 8;
        if (f < 256) {
            int k = f;
            shp = sh0; shstride = 1; shoff = 0;
            rbp = (const float4*)rb0; rbstride4 = 64; kq = k >> 2;
            obase = (long)atom * 256 + k;
        } else if (f < 832) {
            int r = f - 256; int m = r / 192; int k = r - 192 * m;
            shp = sh1; shstride = 3; shoff = m;
            rbp = (const float4*)rb1; rbstride4 = 48; kq = k >> 2;
            obase = B1 + (long)atom * 576 + (long)m * 192 + k;
        } else if (f < 1472) {
            int r = f - 832; int m = r >> 7; int k = r & 127;
            shp = sh2; shstride = 5; shoff = m;
            rbp = (const float4*)rb2; rbstride4 = 32; kq = k >> 2;
            obase = B2 + (long)atom * 640 + (long)m * 128 + k;
        } else {
            int r = f - 1472; int m = r >> 6; int k = r & 63;
            shp = sh3; shstride = 7; shoff = m;
            rbp = (const float4*)rb3; rbstride4 = 16; kq = k >> 2;
            obase = B3 + (long)atom * 448 + (long)m * 64 + k;
        }
    }

    float acc0 = 0.f, acc1 = 0.f, acc2 = 0.f, acc3 = 0.f;
    float acc4 = 0.f, acc5 = 0.f, acc6 = 0.f, acc7 = 0.f;

    const int start = g_offsets[atom];
    const int cnt   = g_count[atom];
    const float4* __restrict__ emb4 = (const float4*)emb;

    for (int base = 0; base < cnt; base += CHUNK) {
        const int n = min(CHUNK, cnt - base);
        // Stage edge ids + neighbor ids (breaks the dependent index chain)
        for (int i = tid; i < n; i += 256) {
            int e = g_edge_order[start + base + i];
            s_e[i]   = e;
            s_nbr[i] = neighbors[e];
        }
        __syncthreads();

        if (active) {
            #pragma unroll 4
            for (int i = 0; i < n; i++) {
                const int  e   = s_e[i];
                const int  nbr = s_nbr[i];
                const float s  = __ldg(shp + (long)e * shstride + shoff);
                const float4 a0 = rbp[(long)e * rbstride4 + kq];
                const float4 a1 = rbp[(long)e * rbstride4 + kq + 1];
                const float4 b0 = emb4[(long)nbr * 64 + kq];
                const float4 b1 = emb4[(long)nbr * 64 + kq + 1];
                acc0 += s * (a0.x * b0.x);
                acc1 += s * (a0.y * b0.y);
                acc2 += s * (a0.z * b0.z);
                acc3 += s * (a0.w * b0.w);
                acc4 += s * (a1.x * b1.x);
                acc5 += s * (a1.y * b1.y);
                acc6 += s * (a1.z * b1.z);
                acc7 += s * (a1.w * b1.w);
            }
        }
        __syncthreads();
    }

    if (active) {
        float4* o = (float4*)(out + obase);
        o[0] = make_float4(acc0, acc1, acc2, acc3);
        o[1] = make_float4(acc4, acc5, acc6, acc7);
    }
}

// ---------------------------------------------------------------------------
extern "C" void kernel_launch(void* const* d_in, const int* in_sizes, int n_in,
                              void* d_out, int out_size)
{
    const float* sh[4];
    const float* rb[4];
    const bool interleaved = ((long)in_sizes[1] > (long)in_sizes[0] * 8);
    for (int l = 0; l < 4; l++) {
        if (interleaved) {
            sh[l] = (const float*)d_in[2 * l];
            rb[l] = (const float*)d_in[2 * l + 1];
        } else {
            sh[l] = (const float*)d_in[l];
            rb[l] = (const float*)d_in[4 + l];
        }
    }
    const float* emb       = (const float*)d_in[8];
    const int*   centers   = (const int*)d_in[9];
    const int*   neighbors = (const int*)d_in[10];
    float*       out       = (float*)d_out;

    const int E      = in_sizes[9];
    const int nAtoms = in_sizes[8] / 256;

    const int TB = 256;
    reset_kernel  <<<(nAtoms + TB - 1) / TB, TB>>>(nAtoms);
    count_kernel  <<<(E + TB - 1) / TB, TB>>>(centers, E);
    scan_kernel   <<<1, 1024>>>(nAtoms);
    scatter_kernel<<<(E + TB - 1) / TB, TB>>>(centers, E);
    density_kernel<<<nAtoms, 256>>>(sh[0], sh[1], sh[2], sh[3],
                                    rb[0], rb[1], rb[2], rb[3],
                                    emb, neighbors, out, nAtoms);
}